// round 17
// baseline (speedup 1.0000x reference)
#include <cuda_runtime.h>
#include <stdint.h>

#define Bn 32
#define Nn 512
#define Pn 128

// ---- helpers --------------------------------------------------------------
__device__ __forceinline__ uint32_t pack_bf16x2(float hi, float lo) {
    uint32_t d;
    asm("cvt.rn.bf16x2.f32 %0, %1, %2;" : "=r"(d) : "f"(hi), "f"(lo));
    return d;
}
__device__ __forceinline__ float bf_lo(uint32_t u) {
    return __uint_as_float(u << 16);
}
__device__ __forceinline__ float bf_hi(uint32_t u) {
    return __uint_as_float(u & 0xFFFF0000u);
}

// bf16 mma m16n8k16: D(fp32) += A(bf16) @ B(bf16)
__device__ __forceinline__ void mma_bf16(float* c, const uint32_t* a,
                                         uint32_t b0, uint32_t b1) {
    asm volatile(
        "mma.sync.aligned.m16n8k16.row.col.f32.bf16.bf16.f32 "
        "{%0,%1,%2,%3}, {%4,%5,%6,%7}, {%8,%9}, {%0,%1,%2,%3};"
        : "+f"(c[0]), "+f"(c[1]), "+f"(c[2]), "+f"(c[3])
        : "r"(a[0]), "r"(a[1]), "r"(a[2]), "r"(a[3]), "r"(b0), "r"(b1));
}

__device__ __forceinline__ void cpasync16(uint32_t dst, const void* src) {
    asm volatile("cp.async.cg.shared.global [%0], [%1], 16;"
                 :: "r"(dst), "l"(src));
}
__device__ __forceinline__ void cpasync_commit() {
    asm volatile("cp.async.commit_group;");
}

// ---------------------------------------------------------------------------
// Single fused kernel. Grid (8 j-tiles, 32 b) x 256 threads (8 warps: 2M x 4N).
//   S[64 j][128 k'] = adj @ mu   (bf16-split MMA, 64-k chunks, 1 sync/iter,
//                                 pos/neg LDGs hoisted before the pipeline wait)
//   D = S @ W2                   (single 128-k pass; W2 staged via cp.async
//                                 overlapped with mainloop tail + S-pack)
//   out = relu(x*W1 + D + pos*vp + neg*vn + cb)
//
// smem (float units), ~107 KB -> 2 CTA/SM:
//   pipeline: As 2x[64][68]=8704 | Mu 2x[64][132]=16896
//   epilogue overlay: Sh [64][68] | Sl [64][68] | W2s [128][132]=16896
// ---------------------------------------------------------------------------
#define AS_OFF  0
#define AS_BUF  4352
#define MU_OFF  8704
#define MU_BUF  8448
#define SH_OFF  0
#define SL_OFF  4352
#define W2S_OFF 8704
#define W1S_OFF 25600
#define VPS_OFF 25728
#define VNS_OFF 25856
#define CBS_OFF 25984
#define PNB_OFF 26112
#define POS_OFF 26624
#define NEG_OFF 26688
#define SMF_TOT 26752

__global__ __launch_bounds__(256, 2) void s2v_kernel(
    const float* __restrict__ adj, const float* __restrict__ weight,
    const float* __restrict__ mu, const float* __restrict__ x,
    const float* __restrict__ W1, const float* __restrict__ W2,
    const float* __restrict__ W3, const float* __restrict__ theta4,
    const float* __restrict__ b1, const float* __restrict__ b2,
    const float* __restrict__ b3, float* __restrict__ out) {
    extern __shared__ float sm[];
    uint32_t smu = (uint32_t)__cvta_generic_to_shared(sm);

    int tid = threadIdx.x;
    int warp = tid >> 5;
    int lane = tid & 31;
    int warpM = warp >> 2;            // 0..1
    int warpN = warp & 3;             // 0..3
    int g4 = lane >> 2;               // 0..7
    int t4 = lane & 3;                // 0..3
    int b = blockIdx.y;
    int j0 = blockIdx.x * 64;

    const float* adj_b = adj + (size_t)b * Nn * Nn;
    const float* w_b   = weight + (size_t)b * Nn * Nn;
    const float* mu_b  = mu + (size_t)b * Nn * Pn;

    int jj = tid & 63;                // pos/neg column
    int ks = tid >> 6;                // 0..3 -> k-subrange ks*16..+15

    // ---- staging: one 64-k chunk (12 x 16B cp.async per thread) ----
    auto stage = [&](int chunk, int buf) {
        int k0 = chunk * 64;
        uint32_t asb = smu + (AS_OFF + buf * AS_BUF) * 4;
        #pragma unroll
        for (int s = 0; s < 4; ++s) {
            int idx = tid + s * 256;           // 0..1023
            int row = idx >> 4;
            int q = idx & 15;
            cpasync16(asb + (row * 68 + q * 4) * 4,
                      &adj_b[(size_t)(j0 + row) * Nn + k0 + q * 4]);
        }
        uint32_t mub = smu + (MU_OFF + buf * MU_BUF) * 4;
        #pragma unroll
        for (int s = 0; s < 8; ++s) {
            int idx = tid + s * 256;           // 0..2047
            int k = idx >> 5;
            int c = idx & 31;
            cpasync16(mub + (k * 132 + c * 4) * 4,
                      &mu_b[(size_t)(k0 + k) * Pn + c * 4]);
        }
    };
    // ---- W2 half staging into overlay (rows h*64..h*64+63) ----
    auto stage_w2 = [&](int h) {
        #pragma unroll
        for (int s = 0; s < 8; ++s) {
            int idx = tid + s * 256;           // 0..2047
            int k = idx >> 5;
            int c = idx & 31;
            cpasync16(smu + (W2S_OFF + (h * 64 + k) * 132 + c * 4) * 4,
                      &W2[(size_t)(h * 64 + k) * Pn + c * 4]);
        }
    };

    stage(0, 0);
    cpasync_commit();

    // ---- prep (overlapped with chunk-0 fill): vp/vn/cb/W1 ----
    if (tid < 128) {
        int p = tid;
        float vp = 0.f, vn = 0.f;
        #pragma unroll 8
        for (int q = 0; q < Pn; ++q) {
            float t = theta4[q];
            float w = W3[q * Pn + p];
            vp += fmaxf(t, 0.f) * w;
            vn += fmaxf(-t, 0.f) * w;
        }
        sm[VPS_OFF + p] = vp;
        sm[VNS_OFF + p] = vn;
        sm[CBS_OFF + p] = b1[p] + b2[p] + b3[p];
        sm[W1S_OFF + p] = W1[p];
    }

    float C[2][4][4];
    #pragma unroll
    for (int mt = 0; mt < 2; ++mt)
        #pragma unroll
        for (int nt = 0; nt < 4; ++nt)
            #pragma unroll
            for (int c = 0; c < 4; ++c) C[mt][nt][c] = 0.f;
    float posr = 0.f, negr = 0.f;

    // ================= mainloop: S = adj @ mu (8 x 64-k chunks) ============
    for (int chunk = 0; chunk < 8; ++chunk) {
        int cur = chunk & 1;
        int k0 = chunk * 64;

        // prefetch pos/neg weights half 0 BEFORE the wait: latency hidden
        // under wait + sync + staging + first MMA block
        float wv0[8];
        #pragma unroll
        for (int s = 0; s < 8; ++s)
            wv0[s] = w_b[(size_t)(k0 + ks * 16 + s) * Nn + j0 + jj];

        asm volatile("cp.async.wait_group 0;");
        __syncthreads();   // fetch(chunk) visible; all reads of buf cur^1 done

        if (chunk < 7) {
            stage(chunk + 1, cur ^ 1);
            cpasync_commit();
        } else {
            stage_w2(0);   // W2 rows 0..63 -> dead Mu-buf0 region
            cpasync_commit();
        }

        const float* As_ = sm + AS_OFF + cur * AS_BUF;
        const float* Mu_ = sm + MU_OFF + cur * MU_BUF;

        // ---- MMA kk = 0,1 (hides wv0 tail + staging) ----
        #pragma unroll
        for (int kk = 0; kk < 2; ++kk) {
            int kb = kk * 16;
            uint32_t afr[2][4];
            #pragma unroll
            for (int mt = 0; mt < 2; ++mt) {
                int r = warpM * 32 + mt * 16 + g4;
                int c = kb + 2 * t4;
                float2 f0 = *(const float2*)&As_[r * 68 + c];
                float2 f1 = *(const float2*)&As_[(r + 8) * 68 + c];
                float2 f2 = *(const float2*)&As_[r * 68 + c + 8];
                float2 f3 = *(const float2*)&As_[(r + 8) * 68 + c + 8];
                afr[mt][0] = pack_bf16x2(f0.y, f0.x);   // adj exact in bf16
                afr[mt][1] = pack_bf16x2(f1.y, f1.x);
                afr[mt][2] = pack_bf16x2(f2.y, f2.x);
                afr[mt][3] = pack_bf16x2(f3.y, f3.x);
            }
            #pragma unroll
            for (int nt = 0; nt < 4; ++nt) {
                int p = warpN * 32 + nt * 8 + g4;
                float m0 = Mu_[(kb + 2 * t4) * 132 + p];
                float m1 = Mu_[(kb + 2 * t4 + 1) * 132 + p];
                float m2 = Mu_[(kb + 2 * t4 + 8) * 132 + p];
                float m3 = Mu_[(kb + 2 * t4 + 9) * 132 + p];
                uint32_t bh0 = pack_bf16x2(m1, m0);
                uint32_t bh1 = pack_bf16x2(m3, m2);
                uint32_t bl0 = pack_bf16x2(m1 - bf_hi(bh0), m0 - bf_lo(bh0));
                uint32_t bl1 = pack_bf16x2(m3 - bf_hi(bh1), m2 - bf_lo(bh1));
                #pragma unroll
                for (int mt = 0; mt < 2; ++mt) {
                    mma_bf16(C[mt][nt], afr[mt], bh0, bh1);
                    mma_bf16(C[mt][nt], afr[mt], bl0, bl1);
                }
            }
        }

        // consume half 0; prefetch half 1 (hidden under kk = 2,3)
        #pragma unroll
        for (int s = 0; s < 8; ++s) {
            float a = As_[jj * 68 + ks * 16 + s];   // exactly 0/1
            posr += a * fmaxf(wv0[s], 0.f);
            negr += a * fmaxf(-wv0[s], 0.f);
        }
        float wv1[8];
        #pragma unroll
        for (int s = 0; s < 8; ++s)
            wv1[s] = w_b[(size_t)(k0 + ks * 16 + 8 + s) * Nn + j0 + jj];

        // ---- MMA kk = 2,3 ----
        #pragma unroll
        for (int kk = 2; kk < 4; ++kk) {
            int kb = kk * 16;
            uint32_t afr[2][4];
            #pragma unroll
            for (int mt = 0; mt < 2; ++mt) {
                int r = warpM * 32 + mt * 16 + g4;
                int c = kb + 2 * t4;
                float2 f0 = *(const float2*)&As_[r * 68 + c];
                float2 f1 = *(const float2*)&As_[(r + 8) * 68 + c];
                float2 f2 = *(const float2*)&As_[r * 68 + c + 8];
                float2 f3 = *(const float2*)&As_[(r + 8) * 68 + c + 8];
                afr[mt][0] = pack_bf16x2(f0.y, f0.x);
                afr[mt][1] = pack_bf16x2(f1.y, f1.x);
                afr[mt][2] = pack_bf16x2(f2.y, f2.x);
                afr[mt][3] = pack_bf16x2(f3.y, f3.x);
            }
            #pragma unroll
            for (int nt = 0; nt < 4; ++nt) {
                int p = warpN * 32 + nt * 8 + g4;
                float m0 = Mu_[(kb + 2 * t4) * 132 + p];
                float m1 = Mu_[(kb + 2 * t4 + 1) * 132 + p];
                float m2 = Mu_[(kb + 2 * t4 + 8) * 132 + p];
                float m3 = Mu_[(kb + 2 * t4 + 9) * 132 + p];
                uint32_t bh0 = pack_bf16x2(m1, m0);
                uint32_t bh1 = pack_bf16x2(m3, m2);
                uint32_t bl0 = pack_bf16x2(m1 - bf_hi(bh0), m0 - bf_lo(bh0));
                uint32_t bl1 = pack_bf16x2(m3 - bf_hi(bh1), m2 - bf_lo(bh1));
                #pragma unroll
                for (int mt = 0; mt < 2; ++mt) {
                    mma_bf16(C[mt][nt], afr[mt], bh0, bh1);
                    mma_bf16(C[mt][nt], afr[mt], bl0, bl1);
                }
            }
        }

        // consume half 1
        #pragma unroll
        for (int s = 0; s < 8; ++s) {
            float a = As_[jj * 68 + ks * 16 + 8 + s];
            posr += a * fmaxf(wv1[s], 0.f);
            negr += a * fmaxf(-wv1[s], 0.f);
        }
        // no trailing sync: next iter's wait+sync protects buffer reuse
    }

    // ================= pack S -> smem; W2 half1 staged under it ============
    __syncthreads();   // mainloop reads done (Mu-buf1, As bufs now dead)
    stage_w2(1);       // W2 rows 64..127 -> former Mu-buf1 region
    cpasync_commit();

    #pragma unroll
    for (int mt = 0; mt < 2; ++mt) {
        int rb = warpM * 32 + mt * 16;
        #pragma unroll
        for (int nt = 0; nt < 4; ++nt) {
            int kp = warpN * 16 + nt * 4 + t4;
            float c0 = C[mt][nt][0], c1 = C[mt][nt][1];   // row rb+g4
            float c2 = C[mt][nt][2], c3 = C[mt][nt][3];   // row rb+g4+8
            uint32_t h0 = pack_bf16x2(c1, c0);
            uint32_t l0 = pack_bf16x2(c1 - bf_hi(h0), c0 - bf_lo(h0));
            uint32_t h1 = pack_bf16x2(c3, c2);
            uint32_t l1 = pack_bf16x2(c3 - bf_hi(h1), c2 - bf_lo(h1));
            sm[SH_OFF + (rb + g4) * 68 + kp]     = __uint_as_float(h0);
            sm[SL_OFF + (rb + g4) * 68 + kp]     = __uint_as_float(l0);
            sm[SH_OFF + (rb + g4 + 8) * 68 + kp] = __uint_as_float(h1);
            sm[SL_OFF + (rb + g4 + 8) * 68 + kp] = __uint_as_float(l1);
        }
    }

    // ================= D = S @ W2 (single 128-k pass, 3-term split) ========
    float D[2][4][4];
    #pragma unroll
    for (int mt = 0; mt < 2; ++mt)
        #pragma unroll
        for (int nt = 0; nt < 4; ++nt)
            #pragma unroll
            for (int c = 0; c < 4; ++c) D[mt][nt][c] = 0.f;

    asm volatile("cp.async.wait_group 0;");
    __syncthreads();   // W2 staged + S-pack visible

    #pragma unroll
    for (int kk2 = 0; kk2 < 8; ++kk2) {
        uint32_t ah[2][4], al[2][4];
        #pragma unroll
        for (int mt = 0; mt < 2; ++mt) {
            int r = warpM * 32 + mt * 16 + g4;
            int base = kk2 * 8 + t4;
            ah[mt][0] = __float_as_uint(sm[SH_OFF + r * 68 + base]);
            ah[mt][1] = __float_as_uint(sm[SH_OFF + (r + 8) * 68 + base]);
            ah[mt][2] = __float_as_uint(sm[SH_OFF + r * 68 + base + 4]);
            ah[mt][3] = __float_as_uint(sm[SH_OFF + (r + 8) * 68 + base + 4]);
            al[mt][0] = __float_as_uint(sm[SL_OFF + r * 68 + base]);
            al[mt][1] = __float_as_uint(sm[SL_OFF + (r + 8) * 68 + base]);
            al[mt][2] = __float_as_uint(sm[SL_OFF + r * 68 + base + 4]);
            al[mt][3] = __float_as_uint(sm[SL_OFF + (r + 8) * 68 + base + 4]);
        }
        #pragma unroll
        for (int nt = 0; nt < 4; ++nt) {
            int p = warpN * 32 + nt * 8 + g4;
            int kl = kk2 * 16 + 2 * t4;
            float w0 = sm[W2S_OFF + kl * 132 + p];
            float w1 = sm[W2S_OFF + (kl + 1) * 132 + p];
            float w2 = sm[W2S_OFF + (kl + 8) * 132 + p];
            float w3 = sm[W2S_OFF + (kl + 9) * 132 + p];
            uint32_t bh0 = pack_bf16x2(w1, w0);
            uint32_t bh1 = pack_bf16x2(w3, w2);
            uint32_t bl0 = pack_bf16x2(w1 - bf_hi(bh0), w0 - bf_lo(bh0));
            uint32_t bl1 = pack_bf16x2(w3 - bf_hi(bh1), w2 - bf_lo(bh1));
            #pragma unroll
            for (int mt = 0; mt < 2; ++mt) {
                mma_bf16(D[mt][nt], ah[mt], bh0, bh1);
                mma_bf16(D[mt][nt], ah[mt], bl0, bl1);
                mma_bf16(D[mt][nt], al[mt], bh0, bh1);
            }
        }
    }

    // ================= pos/neg reduction (deterministic) ===================
    __syncthreads();
    sm[PNB_OFF + ks * 64 + jj]       = posr;
    sm[PNB_OFF + 256 + ks * 64 + jj] = negr;
    __syncthreads();
    if (tid < 64) {
        const float* p = sm + PNB_OFF;
        sm[POS_OFF + tid] = (p[tid] + p[64 + tid]) + (p[128 + tid] + p[192 + tid]);
    } else if (tid < 128) {
        int j = tid - 64;
        const float* p = sm + PNB_OFF + 256;
        sm[NEG_OFF + j] = (p[j] + p[64 + j]) + (p[128 + j] + p[192 + j]);
    }
    __syncthreads();

    // ================= final epilogue ======================================
    const float* W1s = sm + W1S_OFF;
    const float* vps = sm + VPS_OFF;
    const float* vns = sm + VNS_OFF;
    const float* cbs = sm + CBS_OFF;
    #pragma unroll
    for (int mt = 0; mt < 2; ++mt) {
        #pragma unroll
        for (int half = 0; half < 2; ++half) {
            int j = warpM * 32 + mt * 16 + g4 + half * 8;
            int gj = j0 + j;
            float xv = x[b * Nn + gj];
            float pj = sm[POS_OFF + j];
            float nj = sm[NEG_OFF + j];
            #pragma unroll
            for (int nt = 0; nt < 4; ++nt) {
                int p = warpN * 32 + nt * 8 + 2 * t4;
                float c0 = D[mt][nt][half * 2 + 0];
                float c1 = D[mt][nt][half * 2 + 1];
                float2 o;
                o.x = fmaxf(xv * W1s[p] + c0 + pj * vps[p] + nj * vns[p] + cbs[p], 0.f);
                o.y = fmaxf(xv * W1s[p + 1] + c1 + pj * vps[p + 1] + nj * vns[p + 1] + cbs[p + 1], 0.f);
                *(float2*)&out[((size_t)b * Nn + gj) * Pn + p] = o;
            }
        }
    }
}

// ---------------------------------------------------------------------------
extern "C" void kernel_launch(void* const* d_in, const int* in_sizes, int n_in,
                              void* d_out, int out_size) {
    const float* x      = (const float*)d_in[0];
    const float* mu     = (const float*)d_in[1];
    const float* weight = (const float*)d_in[2];
    const float* adj    = (const float*)d_in[3];
    const float* W1     = (const float*)d_in[4];
    const float* b1     = (const float*)d_in[5];
    const float* W2     = (const float*)d_in[6];
    const float* b2     = (const float*)d_in[7];
    const float* W3     = (const float*)d_in[8];
    const float* b3     = (const float*)d_in[9];
    const float* theta4 = (const float*)d_in[10];
    float* out = (float*)d_out;

    const int smem_bytes = SMF_TOT * 4;   // 107008 B
    static int configured = -1;
    if (configured < 0) {
        cudaFuncSetAttribute(s2v_kernel,
                             cudaFuncAttributeMaxDynamicSharedMemorySize,
                             smem_bytes);
        configured = 1;
    }

    dim3 grid(Nn / 64, Bn);
    s2v_kernel<<<grid, 256, smem_bytes>>>(adj, weight, mu, x, W1, W2, W3,
                                          theta4, b1, b2, b3, out);
}